// round 2
// baseline (speedup 1.0000x reference)
#include <cuda_runtime.h>
#include <cstdint>

#define TWO_PI_F 6.283185307179586f
#define S_TOTAL 1024
#define Dm 96
#define Din 64
#define NBg 8
#define WELEM (Dm * Dm)          // 9216
#define CHUNK 128

typedef unsigned long long u64;

// Scratch: per-position weight matrices, layout W[s][j][i] (i contiguous)
__device__ float g_W1[(size_t)S_TOTAL * WELEM];
__device__ float g_W2[(size_t)S_TOTAL * WELEM];
// Pre-transposed static matrices: [k][i], i contiguous (coalesced LDG per k-row)
__device__ float gM1T[Din * Dm];
__device__ float gWrT[Din * Dm];
__device__ float gM2T[Dm * Dm];

__device__ __forceinline__ u64 f2fma(u64 a, u64 b, u64 c) {
    u64 d; asm("fma.rn.f32x2 %0, %1, %2, %3;" : "=l"(d) : "l"(a), "l"(b), "l"(c)); return d;
}
__device__ __forceinline__ u64 f2add(u64 a, u64 b) {
    u64 d; asm("add.rn.f32x2 %0, %1, %2;" : "=l"(d) : "l"(a), "l"(b)); return d;
}
__device__ __forceinline__ u64 pk2(float lo, float hi) {
    u64 r; asm("mov.b64 %0, {%1, %2};" : "=l"(r) : "f"(lo), "f"(hi)); return r;
}
__device__ __forceinline__ void up2(u64 v, float& lo, float& hi) {
    asm("mov.b64 {%0, %1}, %2;" : "=f"(lo), "=f"(hi) : "l"(v));
}

__device__ __forceinline__ float warp_sum(float v) {
    v += __shfl_xor_sync(0xffffffffu, v, 16);
    v += __shfl_xor_sync(0xffffffffu, v, 8);
    v += __shfl_xor_sync(0xffffffffu, v, 4);
    v += __shfl_xor_sync(0xffffffffu, v, 2);
    v += __shfl_xor_sync(0xffffffffu, v, 1);
    return v;
}

// ---------------------------------------------------------------------------
// Kernel 1: W[s,i,j] = sum_g P[i,j,g]*cos(2*pi*s/T), T=(i*96+j)*8+g+2 via
// Chebyshev recurrence, packed f32x2 math. Also transposes M1/Wres1/M2.
// grid: (36, 8, 2), block 256.
// ---------------------------------------------------------------------------
__global__ void __launch_bounds__(256) precompute_W(
    const float* __restrict__ P1, const float* __restrict__ P2,
    const float* __restrict__ M1, const float* __restrict__ Wr,
    const float* __restrict__ M2)
{
    const int e = blockIdx.x * 256 + threadIdx.x;       // 0..9215

    // fold static-matrix transposes into one launch (any copy of the work
    // done by the (y=0,z=0) slice only)
    if (blockIdx.y == 0 && blockIdx.z == 0) {
        if (e < Dm * Din) {
            int i = e / Din, k = e - i * Din;
            gM1T[k * Dm + i] = M1[e];
            gWrT[k * Dm + i] = Wr[e];
        }
        if (e < Dm * Dm) {
            int i = e / Dm, k = e - i * Dm;
            gM2T[k * Dm + i] = M2[e];
        }
    }

    const float* __restrict__ P = blockIdx.z ? P2 : P1;
    float* __restrict__ Wg = blockIdx.z ? g_W2 : g_W1;
    const int i = e % Dm;
    const int j = e / Dm;
    const int base = (i * Dm + j) * NBg;
    const int s0 = blockIdx.y * CHUNK;

    float c[NBg], q[NBg], a2[NBg];
#pragma unroll
    for (int g = 0; g < NBg; g++) {
        float T = (float)(base + g + 2);
        float invT = 1.0f / T;
        a2[g] = 2.0f * cosf(TWO_PI_F * invT);
        c[g]  = cosf(TWO_PI_F * (fmodf((float)s0, T) * invT));
        q[g]  = cosf(TWO_PI_F * (fmodf((float)(s0 - 1), T) * invT));
    }

    u64 C[4], N[4], A[4], Pp[4];
#pragma unroll
    for (int h = 0; h < 4; h++) {
        C[h]  = pk2(c[2*h], c[2*h+1]);
        N[h]  = pk2(-q[2*h], -q[2*h+1]);
        A[h]  = pk2(a2[2*h], a2[2*h+1]);
        Pp[h] = pk2(P[base + 2*h], P[base + 2*h + 1]);
    }

    float* __restrict__ outp = Wg + (size_t)s0 * WELEM + e;
#pragma unroll 4
    for (int s = 0; s < CHUNK; s++) {
        u64 acc0 = f2fma(Pp[0], C[0], f2fma(Pp[1], C[1], 0ULL));
        u64 acc1 = f2fma(Pp[2], C[2], f2fma(Pp[3], C[3], 0ULL));
        u64 t = f2add(acc0, acc1);
        float lo, hi; up2(t, lo, hi);
        outp[(size_t)s * WELEM] = lo + hi;
#pragma unroll
        for (int h = 0; h < 4; h++) {
            u64 cn = f2fma(A[h], C[h], N[h]);          // c_{s+1} = a2*c - c_{s-1}
            N[h] = C[h] ^ 0x8000000080000000ULL;       // -c_s   (ALU pipe)
            C[h] = cn;
        }
    }
}

// ---------------------------------------------------------------------------
// Kernel 2: fused layers. One block (64 thr, 2 warps) per position s.
// Warp w handles batches [4w, 4w+4); lanes own i in {lane, lane+32, lane+64}.
// W read via coalesced LDG from L2; M via LDG from pre-transposed globals.
// xn/x1 kept in smem transposed [j][4b] -> one uniform LDS.128 broadcast
// feeds 12 FMAs.
// ---------------------------------------------------------------------------
__global__ void __launch_bounds__(64) layers_kernel(
    const float* __restrict__ seq,
    const float* __restrict__ g1v, const float* __restrict__ b1v,
    const float* __restrict__ g2v, const float* __restrict__ b2v,
    float* __restrict__ out)
{
    __shared__ __align__(16) float sxq[Din * 8];      // [k][b]
    __shared__ __align__(16) float sxn[2][Dm * 4];    // per-warp [j][bl]
    __shared__ __align__(16) float sx1[2][Dm * 4];

    const int s = blockIdx.x;
    const int tid = threadIdx.x;
    const int w = tid >> 5;
    const int lane = tid & 31;

    // stage seq rows for all 8 batches (coalesced)
#pragma unroll
    for (int b = 0; b < 8; b++)
        sxq[tid * 8 + b] = seq[((size_t)b * S_TOTAL + s) * Din + tid];
    __syncthreads();

    const int i0 = lane, i1 = lane + 32, i2 = lane + 64;
    const int b0 = w * 4;
    float* snw = sxn[w];
    float* s1w = sx1[w];

    const float G1[3] = {__ldg(g1v + i0), __ldg(g1v + i1), __ldg(g1v + i2)};
    const float B1[3] = {__ldg(b1v + i0), __ldg(b1v + i1), __ldg(b1v + i2)};
    const float G2[3] = {__ldg(g2v + i0), __ldg(g2v + i1), __ldg(g2v + i2)};
    const float B2[3] = {__ldg(b2v + i0), __ldg(b2v + i1), __ldg(b2v + i2)};

    // ---- layer 1: xt = M1 x, res = Wres1 x (4 batches per warp) ----
    float xt[12], rs_[12];
#pragma unroll
    for (int q = 0; q < 12; q++) { xt[q] = 0.f; rs_[q] = 0.f; }
    {
        const float* xb = sxq + b0;
#pragma unroll 4
        for (int k = 0; k < Din; k++) {
            const float* mrow = gM1T + k * Dm;
            const float* rrow = gWrT + k * Dm;
            float m0 = __ldg(mrow + i0), m1 = __ldg(mrow + i1), m2 = __ldg(mrow + i2);
            float r0 = __ldg(rrow + i0), r1 = __ldg(rrow + i1), r2 = __ldg(rrow + i2);
            float4 xk = *(const float4*)(xb + k * 8);
            xt[0] = fmaf(m0, xk.x, xt[0]); xt[1] = fmaf(m1, xk.x, xt[1]); xt[2] = fmaf(m2, xk.x, xt[2]);
            xt[3] = fmaf(m0, xk.y, xt[3]); xt[4] = fmaf(m1, xk.y, xt[4]); xt[5] = fmaf(m2, xk.y, xt[5]);
            xt[6] = fmaf(m0, xk.z, xt[6]); xt[7] = fmaf(m1, xk.z, xt[7]); xt[8] = fmaf(m2, xk.z, xt[8]);
            xt[9] = fmaf(m0, xk.w, xt[9]); xt[10]= fmaf(m1, xk.w, xt[10]);xt[11]= fmaf(m2, xk.w, xt[11]);
            rs_[0] = fmaf(r0, xk.x, rs_[0]); rs_[1] = fmaf(r1, xk.x, rs_[1]); rs_[2] = fmaf(r2, xk.x, rs_[2]);
            rs_[3] = fmaf(r0, xk.y, rs_[3]); rs_[4] = fmaf(r1, xk.y, rs_[4]); rs_[5] = fmaf(r2, xk.y, rs_[5]);
            rs_[6] = fmaf(r0, xk.z, rs_[6]); rs_[7] = fmaf(r1, xk.z, rs_[7]); rs_[8] = fmaf(r2, xk.z, rs_[8]);
            rs_[9] = fmaf(r0, xk.w, rs_[9]); rs_[10]= fmaf(r1, xk.w, rs_[10]);rs_[11]= fmaf(r2, xk.w, rs_[11]);
        }
    }

    // ---- LN 1 ----
    float xn[12];
#pragma unroll
    for (int bl = 0; bl < 4; bl++) {
        float a0 = xt[bl*3], a1 = xt[bl*3+1], a2v = xt[bl*3+2];
        float mu = warp_sum(a0 + a1 + a2v) * (1.0f / 96.0f);
        float d0 = a0 - mu, d1 = a1 - mu, d2 = a2v - mu;
        float var = warp_sum(d0*d0 + d1*d1 + d2*d2) * (1.0f / 96.0f);
        float rq = rsqrtf(var + 1e-5f);
        xn[bl*3+0] = fmaf(d0 * rq, G1[0], B1[0]);
        xn[bl*3+1] = fmaf(d1 * rq, G1[1], B1[1]);
        xn[bl*3+2] = fmaf(d2 * rq, G1[2], B1[2]);
    }
    *(float4*)(snw + i0*4) = make_float4(xn[0], xn[3], xn[6], xn[9]);
    *(float4*)(snw + i1*4) = make_float4(xn[1], xn[4], xn[7], xn[10]);
    *(float4*)(snw + i2*4) = make_float4(xn[2], xn[5], xn[8], xn[11]);
    __syncwarp();

    // ---- Nk1 = W1[s] @ xn, x1 = Nk1 + res ----
    float x1[12];
#pragma unroll
    for (int q = 0; q < 12; q++) x1[q] = rs_[q];
    {
        const float* W1r = g_W1 + (size_t)s * WELEM;
#pragma unroll 2
        for (int j = 0; j < Dm; j++) {
            const float* wr = W1r + j * Dm;
            float w0 = __ldg(wr + i0), w1 = __ldg(wr + i1), w2 = __ldg(wr + i2);
            float4 xj = *(const float4*)(snw + j * 4);
            x1[0] = fmaf(w0, xj.x, x1[0]); x1[1] = fmaf(w1, xj.x, x1[1]); x1[2] = fmaf(w2, xj.x, x1[2]);
            x1[3] = fmaf(w0, xj.y, x1[3]); x1[4] = fmaf(w1, xj.y, x1[4]); x1[5] = fmaf(w2, xj.y, x1[5]);
            x1[6] = fmaf(w0, xj.z, x1[6]); x1[7] = fmaf(w1, xj.z, x1[7]); x1[8] = fmaf(w2, xj.z, x1[8]);
            x1[9] = fmaf(w0, xj.w, x1[9]); x1[10]= fmaf(w1, xj.w, x1[10]);x1[11]= fmaf(w2, xj.w, x1[11]);
        }
    }
    *(float4*)(s1w + i0*4) = make_float4(x1[0], x1[3], x1[6], x1[9]);
    *(float4*)(s1w + i1*4) = make_float4(x1[1], x1[4], x1[7], x1[10]);
    *(float4*)(s1w + i2*4) = make_float4(x1[2], x1[5], x1[8], x1[11]);
    __syncwarp();

    // ---- layer 2: xt2 = M2 x1 ----
    float t[12];
#pragma unroll
    for (int q = 0; q < 12; q++) t[q] = 0.f;
    {
#pragma unroll 2
        for (int k = 0; k < Dm; k++) {
            const float* mrow = gM2T + k * Dm;
            float m0 = __ldg(mrow + i0), m1 = __ldg(mrow + i1), m2 = __ldg(mrow + i2);
            float4 xk = *(const float4*)(s1w + k * 4);
            t[0] = fmaf(m0, xk.x, t[0]); t[1] = fmaf(m1, xk.x, t[1]); t[2] = fmaf(m2, xk.x, t[2]);
            t[3] = fmaf(m0, xk.y, t[3]); t[4] = fmaf(m1, xk.y, t[4]); t[5] = fmaf(m2, xk.y, t[5]);
            t[6] = fmaf(m0, xk.z, t[6]); t[7] = fmaf(m1, xk.z, t[7]); t[8] = fmaf(m2, xk.z, t[8]);
            t[9] = fmaf(m0, xk.w, t[9]); t[10]= fmaf(m1, xk.w, t[10]);t[11]= fmaf(m2, xk.w, t[11]);
        }
    }

    // ---- LN 2 ----
#pragma unroll
    for (int bl = 0; bl < 4; bl++) {
        float a0 = t[bl*3], a1 = t[bl*3+1], a2v = t[bl*3+2];
        float mu = warp_sum(a0 + a1 + a2v) * (1.0f / 96.0f);
        float d0 = a0 - mu, d1 = a1 - mu, d2 = a2v - mu;
        float var = warp_sum(d0*d0 + d1*d1 + d2*d2) * (1.0f / 96.0f);
        float rq = rsqrtf(var + 1e-5f);
        xn[bl*3+0] = fmaf(d0 * rq, G2[0], B2[0]);
        xn[bl*3+1] = fmaf(d1 * rq, G2[1], B2[1]);
        xn[bl*3+2] = fmaf(d2 * rq, G2[2], B2[2]);
    }
    *(float4*)(snw + i0*4) = make_float4(xn[0], xn[3], xn[6], xn[9]);
    *(float4*)(snw + i1*4) = make_float4(xn[1], xn[4], xn[7], xn[10]);
    *(float4*)(snw + i2*4) = make_float4(xn[2], xn[5], xn[8], xn[11]);
    __syncwarp();

    // ---- out = W2[s] @ xn2 + x1 ----
    float o[12];
#pragma unroll
    for (int q = 0; q < 12; q++) o[q] = x1[q];
    {
        const float* W2r = g_W2 + (size_t)s * WELEM;
#pragma unroll 2
        for (int j = 0; j < Dm; j++) {
            const float* wr = W2r + j * Dm;
            float w0 = __ldg(wr + i0), w1 = __ldg(wr + i1), w2 = __ldg(wr + i2);
            float4 xj = *(const float4*)(snw + j * 4);
            o[0] = fmaf(w0, xj.x, o[0]); o[1] = fmaf(w1, xj.x, o[1]); o[2] = fmaf(w2, xj.x, o[2]);
            o[3] = fmaf(w0, xj.y, o[3]); o[4] = fmaf(w1, xj.y, o[4]); o[5] = fmaf(w2, xj.y, o[5]);
            o[6] = fmaf(w0, xj.z, o[6]); o[7] = fmaf(w1, xj.z, o[7]); o[8] = fmaf(w2, xj.z, o[8]);
            o[9] = fmaf(w0, xj.w, o[9]); o[10]= fmaf(w1, xj.w, o[10]);o[11]= fmaf(w2, xj.w, o[11]);
        }
    }
#pragma unroll
    for (int bl = 0; bl < 4; bl++) {
        float* op = out + ((size_t)(b0 + bl) * S_TOTAL + s) * Dm;
        op[i0] = o[bl*3+0];
        op[i1] = o[bl*3+1];
        op[i2] = o[bl*3+2];
    }
}

extern "C" void kernel_launch(void* const* d_in, const int* in_sizes, int n_in,
                              void* d_out, int out_size) {
    const float* seq = (const float*)d_in[0];
    const float* M1  = (const float*)d_in[1];
    const float* P1  = (const float*)d_in[2];
    const float* Wr1 = (const float*)d_in[3];
    const float* g1  = (const float*)d_in[4];
    const float* b1  = (const float*)d_in[5];
    const float* M2  = (const float*)d_in[6];
    const float* P2  = (const float*)d_in[7];
    const float* g2  = (const float*)d_in[8];
    const float* b2  = (const float*)d_in[9];
    float* out = (float*)d_out;

    precompute_W<<<dim3(WELEM / 256, S_TOTAL / CHUNK, 2), 256>>>(P1, P2, M1, Wr1, M2);
    layers_kernel<<<S_TOTAL, 64>>>(seq, g1, b1, g2, b2, out);
}